// round 5
// baseline (speedup 1.0000x reference)
#include <cuda_runtime.h>
#include <cuda_bf16.h>
#include <cstdint>

// Problem constants
#define T_DIM   64
#define NCH     2048
#define KDIM    65536
#define THRESHV 16384.0f
#define KWTA    16

// GEMM config
#define SPLITK  16
#define KRANGE  (KDIM / SPLITK)   // 4096 K per CTA
#define BK      16
#define NIT     (KRANGE / BK)     // 256 iterations
#define STAGES  4
// Stage layout (bf16 tiles, 48B padded row stride for conflict-free ldmatrix):
//   A_hi [0,3072)  A_lo [3072,6144)  B_hi [6144,12288)  B_lo [12288,18432)
#define RSTRIDE 48
#define AH_OFF  0
#define AL_OFF  3072
#define BH_OFF  6144
#define BL_OFF  12288
#define STG     18432
#define SMEM_TOTAL (STAGES * STG)   // 73728

// Static scratch (no allocations allowed)
__device__ float g_partial[SPLITK][T_DIM * NCH];   // 8 MB
__device__ float g_pot[T_DIM * NCH];
__device__ float g_coef[NCH];

// ---------------------------------------------------------------------------
// Helpers
// ---------------------------------------------------------------------------
__device__ __forceinline__ uint32_t smem_u32(const void* p) {
    uint32_t a;
    asm("{ .reg .u64 t; cvta.to.shared.u64 t, %1; cvt.u32.u64 %0, t; }"
        : "=r"(a) : "l"(p));
    return a;
}

// Split float2 -> hi bf16x2 (RN) + lo bf16x2 (residual). RN keeps lo zero-mean
// so the dropped lo*lo term adds no bias. (Proven exact in R3/R4.)
__device__ __forceinline__ void split2(float x, float y, uint32_t& h, uint32_t& l) {
    asm("cvt.rn.bf16x2.f32 %0, %1, %2;" : "=r"(h) : "f"(y), "f"(x));
    float hx = __uint_as_float(h << 16);
    float hy = __uint_as_float(h & 0xFFFF0000u);
    float lx = x - hx;
    float ly = y - hy;
    asm("cvt.rn.bf16x2.f32 %0, %1, %2;" : "=r"(l) : "f"(ly), "f"(lx));
}

__device__ __forceinline__ void mma16816(float* c, const uint32_t* a,
                                         uint32_t b0, uint32_t b1) {
    asm volatile(
        "mma.sync.aligned.m16n8k16.row.col.f32.bf16.bf16.f32 "
        "{%0,%1,%2,%3}, {%4,%5,%6,%7}, {%8,%9}, {%0,%1,%2,%3};"
        : "+f"(c[0]), "+f"(c[1]), "+f"(c[2]), "+f"(c[3])
        : "r"(a[0]), "r"(a[1]), "r"(a[2]), "r"(a[3]), "r"(b0), "r"(b1));
}

__device__ __forceinline__ void ldsm4(uint32_t* r, uint32_t addr) {
    asm volatile("ldmatrix.sync.aligned.m8n8.x4.shared.b16 {%0,%1,%2,%3}, [%4];"
                 : "=r"(r[0]), "=r"(r[1]), "=r"(r[2]), "=r"(r[3]) : "r"(addr));
}

// Convert one float4 and store hi/lo bf16x2 pairs (8B each) into smem.
__device__ __forceinline__ void cvt_sts(char* hiP, char* loP, float4 v) {
    uint32_t h0, l0, h1, l1;
    split2(v.x, v.y, h0, l0);
    split2(v.z, v.w, h1, l1);
    *(uint2*)hiP = make_uint2(h0, h1);
    *(uint2*)loP = make_uint2(l0, l1);
}

// ---------------------------------------------------------------------------
// Kernel 1: bf16 HMMA split-K GEMM, convert-once smem + ldmatrix.
//   g_partial[ks][t*NCH + ch] = sum_k rec[t][k] * w[ch][k]
// 256 threads = 2(t) x 4(ch) warps; warp tile 32t x 32ch; CTA tile 64t x 128ch.
// Register LDG pipeline depth 2 over a 4-stage smem ring, 1 barrier/iter.
// ---------------------------------------------------------------------------
__global__ void __launch_bounds__(256, 2)
gemm_mma(const float* __restrict__ rec, const float* __restrict__ w) {
    extern __shared__ char sm[];
    const uint32_t sbase = smem_u32(sm);

    const int tid  = threadIdx.x;
    const int wid  = tid >> 5;
    const int lane = tid & 31;
    const int g    = lane >> 2;        // fragment row group 0..7
    const int q    = lane & 3;         // fragment k quad 0..3
    const int wm   = wid >> 2;         // 0..1  (t block)
    const int wn   = wid & 3;          // 0..3  (ch block)
    const int nblk = blockIdx.x * 128;
    const size_t k0 = (size_t)blockIdx.y * KRANGE;

    // ---- loader role: thread -> A row lr (1 float4) + B rows lr, lr+64 ----
    const int lr  = tid >> 2;
    const int lkc = (tid & 3) * 4;     // k offset of this thread's float4
    const float* aS  = rec + (size_t)lr * KDIM + k0 + lkc;
    const float* bS0 = w + (size_t)(nblk + lr) * KDIM + k0 + lkc;
    const float* bS1 = bS0 + (size_t)64 * KDIM;
    const uint32_t ldOff = (uint32_t)lr * RSTRIDE + lkc * 2;   // byte off in tile

    // ---- ldmatrix per-lane offsets (within a stage) ----
    const int j  = lane >> 3;          // tile index 0..3
    const int l7 = lane & 7;
    // A x4 tiles: j&1 -> m-block(+8), j>>1 -> k-chunk(+16B)
    const uint32_t aOff = (uint32_t)(wm * 32 + (j & 1) * 8 + l7) * RSTRIDE
                        + (j >> 1) * 16 + AH_OFF;
    // B x4 tiles: j>>1 -> n-block(+8), j&1 -> k-chunk(+16B)
    const uint32_t bOff = (uint32_t)(wn * 32 + (j >> 1) * 8 + l7) * RSTRIDE
                        + (j & 1) * 16 + BH_OFF;

    float acc[2][4][4];
    #pragma unroll
    for (int m = 0; m < 2; m++)
        #pragma unroll
        for (int n = 0; n < 4; n++)
            #pragma unroll
            for (int i = 0; i < 4; i++) acc[m][n][i] = 0.0f;

    float4 rbA[2], rbB0[2], rbB1[2];

    // Prologue: LDG chunks 0,1 into reg ring; convert+store chunk 0 -> stage 0;
    // LDG chunk 2 into freed slot.
    rbA[0]  = *(const float4*)(aS);
    rbB0[0] = *(const float4*)(bS0);
    rbB1[0] = *(const float4*)(bS1);
    rbA[1]  = *(const float4*)(aS + 16);
    rbB0[1] = *(const float4*)(bS0 + 16);
    rbB1[1] = *(const float4*)(bS1 + 16);
    {
        char* st = sm;   // stage 0
        cvt_sts(st + AH_OFF + ldOff, st + AL_OFF + ldOff, rbA[0]);
        cvt_sts(st + BH_OFF + ldOff, st + BL_OFF + ldOff, rbB0[0]);
        cvt_sts(st + BH_OFF + 3072 + ldOff, st + BL_OFF + 3072 + ldOff, rbB1[0]);
    }
    rbA[0]  = *(const float4*)(aS + 32);
    rbB0[0] = *(const float4*)(bS0 + 32);
    rbB1[0] = *(const float4*)(bS1 + 32);

    #pragma unroll 1
    for (int it = 0; it < NIT; it++) {
        // 1) convert + store chunk it+1 (held in rb[(it+1)&1]) -> stage (it+1)&3
        if (it < NIT - 1) {
            const int rb = (it + 1) & 1;
            char* st = sm + ((it + 1) & 3) * STG;
            cvt_sts(st + AH_OFF + ldOff, st + AL_OFF + ldOff, rbA[rb]);
            cvt_sts(st + BH_OFF + ldOff, st + BL_OFF + ldOff, rbB0[rb]);
            cvt_sts(st + BH_OFF + 3072 + ldOff, st + BL_OFF + 3072 + ldOff, rbB1[rb]);
        }
        // 2) LDG chunk it+3 into the freed register slot
        if (it < NIT - 3) {
            const int rb = (it + 1) & 1;
            const int co = (it + 3) * BK;
            rbA[rb]  = *(const float4*)(aS + co);
            rbB0[rb] = *(const float4*)(bS0 + co);
            rbB1[rb] = *(const float4*)(bS1 + co);
        }
        // 3) barrier: stage it visible to all; stage (it+1) writes done
        __syncthreads();

        // 4) compute on stage it&3
        const uint32_t sb = sbase + (it & 3) * STG;
        uint32_t Ah0[4], Ah1[4], Al0[4], Al1[4];
        ldsm4(Ah0, sb + aOff);
        ldsm4(Ah1, sb + aOff + 16 * RSTRIDE);
        ldsm4(Al0, sb + aOff + (AL_OFF - AH_OFF));
        ldsm4(Al1, sb + aOff + (AL_OFF - AH_OFF) + 16 * RSTRIDE);
        uint32_t Bh0[4], Bh1[4], Bl0[4], Bl1[4];
        ldsm4(Bh0, sb + bOff);                      // n-tiles 0,1 hi
        ldsm4(Bh1, sb + bOff + 16 * RSTRIDE);       // n-tiles 2,3 hi
        ldsm4(Bl0, sb + bOff + (BL_OFF - BH_OFF));
        ldsm4(Bl1, sb + bOff + (BL_OFF - BH_OFF) + 16 * RSTRIDE);

        const uint32_t* Bh[4] = { &Bh0[0], &Bh0[2], &Bh1[0], &Bh1[2] };
        const uint32_t* Bl[4] = { &Bl0[0], &Bl0[2], &Bl1[0], &Bl1[2] };
        const uint32_t* Ah[2] = { Ah0, Ah1 };
        const uint32_t* Al[2] = { Al0, Al1 };

        #pragma unroll
        for (int m = 0; m < 2; m++) {
            #pragma unroll
            for (int n = 0; n < 4; n++) {
                mma16816(acc[m][n], Ah[m], Bh[n][0], Bh[n][1]);   // hi*hi
                mma16816(acc[m][n], Ah[m], Bl[n][0], Bl[n][1]);   // hi*lo
                mma16816(acc[m][n], Al[m], Bh[n][0], Bh[n][1]);   // lo*hi
            }
        }
    }

    // Epilogue: c0,c1 -> row r0; c2,c3 -> row r0+8; cols 2q, 2q+1
    float* gp = g_partial[blockIdx.y];
    const int t0 = wm * 32;
    #pragma unroll
    for (int m = 0; m < 2; m++) {
        const int r0 = t0 + m * 16 + g;
        #pragma unroll
        for (int n = 0; n < 4; n++) {
            const int cb = nblk + wn * 32 + n * 8 + 2 * q;
            *(float2*)&gp[r0 * NCH + cb]       = make_float2(acc[m][n][0], acc[m][n][1]);
            *(float2*)&gp[(r0 + 8) * NCH + cb] = make_float2(acc[m][n][2], acc[m][n][3]);
        }
    }
}

// ---------------------------------------------------------------------------
// Kernel 2: reduce split-K partials -> g_pot
// ---------------------------------------------------------------------------
__global__ void reduce_kernel() {
    int i = blockIdx.x * blockDim.x + threadIdx.x;
    if (i < T_DIM * NCH) {
        float s = 0.0f;
        #pragma unroll
        for (int p = 0; p < SPLITK; p++) s += g_partial[p][i];
        g_pot[i] = s;
    }
}

// ---------------------------------------------------------------------------
// Kernel 3: winner selection (unchanged — proven exact)
// ---------------------------------------------------------------------------
__global__ void __launch_bounds__(1024)
winners_kernel() {
    __shared__ int   cnt_s[NCH];
    __shared__ float fpv_s[NCH];
    __shared__ float tot_s[NCH];
    __shared__ float rv[1024];
    __shared__ int   ri[1024];

    const int tid = threadIdx.x;

    for (int k = tid; k < NCH; k += 1024) {
        int cnt = 0;
        for (int t = 0; t < T_DIM; t++) {
            float o = g_pot[t * NCH + k];
            if (o > THRESHV) cnt++;
        }
        int fi = T_DIM - cnt;
        if (fi > T_DIM - 1) fi = T_DIM - 1;
        if (fi < 0) fi = 0;
        float o  = g_pot[fi * NCH + k];
        float fp = (o > THRESHV) ? o : 0.0f;
        cnt_s[k] = cnt;
        fpv_s[k] = fp;
    }
    __syncthreads();

    float m = 0.0f;
    for (int k = tid; k < NCH; k += 1024)
        m = fmaxf(m, (cnt_s[k] > 0) ? fpv_s[k] : 0.0f);
    rv[tid] = m;
    __syncthreads();
    for (int s = 512; s > 0; s >>= 1) {
        if (tid < s) rv[tid] = fmaxf(rv[tid], rv[tid + s]);
        __syncthreads();
    }
    float v = rv[0] * (float)T_DIM;
    __syncthreads();

    for (int k = tid; k < NCH; k += 1024) {
        float term = fpv_s[k] + v;
        float s = 0.0f;
        int c = cnt_s[k];
        for (int i = 0; i < c; i++) s += term;
        tot_s[k] = s;
        g_coef[k] = 0.0f;
    }
    __syncthreads();

    for (int it = 0; it < KWTA; it++) {
        float bv = -3.4e38f;
        int   bi = NCH;
        for (int k = tid; k < NCH; k += 1024) {
            float vv = tot_s[k];
            if (vv > bv || (vv == bv && k < bi)) { bv = vv; bi = k; }
        }
        rv[tid] = bv; ri[tid] = bi;
        __syncthreads();
        for (int s = 512; s > 0; s >>= 1) {
            if (tid < s) {
                if (rv[tid + s] > rv[tid] ||
                    (rv[tid + s] == rv[tid] && ri[tid + s] < ri[tid])) {
                    rv[tid] = rv[tid + s];
                    ri[tid] = ri[tid + s];
                }
            }
            __syncthreads();
        }
        if (tid == 0) {
            int wk = ri[0];
            if (rv[0] > 0.0f) g_coef[wk] = 1.0f;
            tot_s[wk] = -3.4e38f;
        }
        __syncthreads();
    }
}

// ---------------------------------------------------------------------------
// Kernel 4: final spikes
// ---------------------------------------------------------------------------
__global__ void output_kernel(float* __restrict__ out) {
    int i = blockIdx.x * blockDim.x + threadIdx.x;
    if (i < T_DIM * NCH) {
        float o = g_pot[i];
        out[i] = (o > THRESHV && g_coef[i & (NCH - 1)] > 0.0f) ? 1.0f : 0.0f;
    }
}

// ---------------------------------------------------------------------------
extern "C" void kernel_launch(void* const* d_in, const int* in_sizes, int n_in,
                              void* d_out, int out_size) {
    const float* rec = (const float*)d_in[0];   // (64, 1, 256, 256)
    const float* w   = (const float*)d_in[1];   // (2048, 1, 256, 256)
    float* out = (float*)d_out;                 // (64, 2048, 1, 1) float32

    cudaFuncSetAttribute(gemm_mma, cudaFuncAttributeMaxDynamicSharedMemorySize,
                         SMEM_TOTAL);
    dim3 grid(NCH / 128, SPLITK);               // (16, 16) = 256 CTAs
    gemm_mma<<<grid, 256, SMEM_TOTAL>>>(rec, w);
    reduce_kernel<<<(T_DIM * NCH + 255) / 256, 256>>>();
    winners_kernel<<<1, 1024>>>();
    output_kernel<<<(T_DIM * NCH + 255) / 256, 256>>>(out);
}

// round 6
// speedup vs baseline: 1.6066x; 1.6066x over previous
#include <cuda_runtime.h>
#include <cuda_bf16.h>
#include <cstdint>

// Problem constants
#define T_DIM   64
#define NCH     2048
#define KDIM    65536
#define THRESHV 16384.0f
#define KWTA    16

// GEMM config
#define SPLITK  16
#define KRANGE  (KDIM / SPLITK)   // 4096 K per CTA
#define BK      16
#define NIT     (KRANGE / BK)     // 256 iterations

// fp32 staging ring: 4 stages x (A 64x16 fp32 = 4KB, B 128x16 fp32 = 8KB)
#define FPSTG   12288
#define FP_B    4096
// bf16 ring: 3 stages x 18432 (AH 0, AL 3072, BH 6144, BL 12288; 48B row stride)
#define BFBASE  49152
#define BFSTG   18432
#define RSTRIDE 48
#define AH_OFF  0
#define AL_OFF  3072
#define BH_OFF  6144
#define BL_OFF  12288
#define SMEM_TOTAL (BFBASE + 3 * BFSTG)   // 104448

// Static scratch (no allocations allowed)
__device__ float g_partial[SPLITK][T_DIM * NCH];   // 8 MB
__device__ float g_pot[T_DIM * NCH];
__device__ float g_coef[NCH];

// ---------------------------------------------------------------------------
// Helpers
// ---------------------------------------------------------------------------
__device__ __forceinline__ uint32_t smem_u32(const void* p) {
    uint32_t a;
    asm("{ .reg .u64 t; cvta.to.shared.u64 t, %1; cvt.u32.u64 %0, t; }"
        : "=r"(a) : "l"(p));
    return a;
}
__device__ __forceinline__ void cp16(uint32_t dst, const void* src) {
    asm volatile("cp.async.cg.shared.global [%0], [%1], 16;"
                 :: "r"(dst), "l"(src) : "memory");
}
#define CP_COMMIT() asm volatile("cp.async.commit_group;" ::: "memory")
#define CP_WAIT(n)  asm volatile("cp.async.wait_group %0;" :: "n"(n) : "memory")

// Split float2 -> hi bf16x2 (RN) + lo bf16x2 (residual). RN keeps lo zero-mean
// so the dropped lo*lo term adds no bias. (Proven exact R3-R5.)
__device__ __forceinline__ void split2(float x, float y, uint32_t& h, uint32_t& l) {
    asm("cvt.rn.bf16x2.f32 %0, %1, %2;" : "=r"(h) : "f"(y), "f"(x));
    float hx = __uint_as_float(h << 16);
    float hy = __uint_as_float(h & 0xFFFF0000u);
    float lx = x - hx;
    float ly = y - hy;
    asm("cvt.rn.bf16x2.f32 %0, %1, %2;" : "=r"(l) : "f"(ly), "f"(lx));
}

__device__ __forceinline__ void mma16816(float* c, const uint32_t* a,
                                         uint32_t b0, uint32_t b1) {
    asm volatile(
        "mma.sync.aligned.m16n8k16.row.col.f32.bf16.bf16.f32 "
        "{%0,%1,%2,%3}, {%4,%5,%6,%7}, {%8,%9}, {%0,%1,%2,%3};"
        : "+f"(c[0]), "+f"(c[1]), "+f"(c[2]), "+f"(c[3])
        : "r"(a[0]), "r"(a[1]), "r"(a[2]), "r"(a[3]), "r"(b0), "r"(b1));
}

__device__ __forceinline__ void ldsm4(uint32_t* r, uint32_t addr) {
    asm volatile("ldmatrix.sync.aligned.m8n8.x4.shared.b16 {%0,%1,%2,%3}, [%4];"
                 : "=r"(r[0]), "=r"(r[1]), "=r"(r[2]), "=r"(r[3]) : "r"(addr));
}

// Convert one float4 from fp32 smem, store hi/lo bf16x2 pairs into bf16 tiles.
__device__ __forceinline__ void cvt_sts(const char* fp, char* hiP, char* loP) {
    float4 v = *(const float4*)fp;
    uint32_t h0, l0, h1, l1;
    split2(v.x, v.y, h0, l0);
    split2(v.z, v.w, h1, l1);
    *(uint2*)hiP = make_uint2(h0, h1);
    *(uint2*)loP = make_uint2(l0, l1);
}

// ---------------------------------------------------------------------------
// Kernel 1: bf16 HMMA split-K GEMM.
//   g_partial[ks][t*NCH + ch] = sum_k rec[t][k] * w[ch][k]
// cp.async fp32 4-stage ring -> convert-once (each thread converts the data
// it staged) -> 3-stage bf16 hi/lo ring -> ldmatrix + 3-term MMA.
// 256 threads = 2(t) x 4(ch) warps; warp tile 32t x 32ch; CTA 64t x 128ch.
// ---------------------------------------------------------------------------
__global__ void __launch_bounds__(256, 2)
gemm_mma(const float* __restrict__ rec, const float* __restrict__ w) {
    extern __shared__ char sm[];
    const uint32_t sbase = smem_u32(sm);

    const int tid  = threadIdx.x;
    const int wid  = tid >> 5;
    const int lane = tid & 31;
    const int g    = lane >> 2;
    const int q    = lane & 3;
    const int wm   = wid >> 2;         // 0..1  (t block)
    const int wn   = wid & 3;          // 0..3  (ch block)
    const int nblk = blockIdx.x * 128;
    const size_t k0 = (size_t)blockIdx.y * KRANGE;

    // ---- loader/converter role: A row lr (1 float4) + B rows lr, lr+64 ----
    const int lr  = tid >> 2;
    const int lkc = (tid & 3) * 4;
    const float* aS  = rec + (size_t)lr * KDIM + k0 + lkc;
    const float* bS0 = w + (size_t)(nblk + lr) * KDIM + k0 + lkc;
    const float* bS1 = bS0 + (size_t)64 * KDIM;
    const uint32_t fpA = (uint32_t)lr * 64 + lkc * 4;          // byte off in fp stage
    const uint32_t fpB = FP_B + (uint32_t)lr * 64 + lkc * 4;
    const uint32_t bfO = (uint32_t)lr * RSTRIDE + lkc * 2;     // byte off in bf tiles

    // ---- ldmatrix per-lane offsets (within a bf16 stage) — R5-verified ----
    const int j  = lane >> 3;
    const int l7 = lane & 7;
    const uint32_t aOff = (uint32_t)(wm * 32 + (j & 1) * 8 + l7) * RSTRIDE
                        + (j >> 1) * 16 + AH_OFF;
    const uint32_t bOff = (uint32_t)(wn * 32 + (j >> 1) * 8 + l7) * RSTRIDE
                        + (j & 1) * 16 + BH_OFF;

    float acc[2][4][4];
    #pragma unroll
    for (int m = 0; m < 2; m++)
        #pragma unroll
        for (int n = 0; n < 4; n++)
            #pragma unroll
            for (int i = 0; i < 4; i++) acc[m][n][i] = 0.0f;

    // Prologue: stage chunks 0..2; convert chunk 0 -> bf stage 0
    #pragma unroll
    for (int s = 0; s < 3; s++) {
        const uint32_t fo = sbase + s * FPSTG;
        const int co = s * BK;
        cp16(fo + fpA, aS + co);
        cp16(fo + fpB, bS0 + co);
        cp16(fo + fpB + 4096, bS1 + co);
        CP_COMMIT();
    }
    CP_WAIT(2);
    {
        const char* fs = sm;
        char* bs = sm + BFBASE;
        cvt_sts(fs + fpA, bs + AH_OFF + bfO, bs + AL_OFF + bfO);
        cvt_sts(fs + fpB, bs + BH_OFF + bfO, bs + BL_OFF + bfO);
        cvt_sts(fs + fpB + 4096, bs + BH_OFF + 3072 + bfO, bs + BL_OFF + 3072 + bfO);
    }

    int bfc = 0;   // compute stage (= it % 3)

    #pragma unroll 1
    for (int it = 0; it < NIT; it++) {
        // 1) prefetch chunk it+3 into fp stage (it+3)&3
        const int nc = it + 3;
        if (nc < NIT) {
            const uint32_t fo = sbase + (nc & 3) * FPSTG;
            const int co = nc * BK;
            cp16(fo + fpA, aS + co);
            cp16(fo + fpB, bS0 + co);
            cp16(fo + fpB + 4096, bS1 + co);
        }
        CP_COMMIT();
        CP_WAIT(2);                      // own chunk it+1 landed
        __syncthreads();                 // all iter-1 compute done; bf stage safe

        // 2) convert chunk it+1 -> bf stage (it+1)%3
        const int bfn = (bfc == 2) ? 0 : bfc + 1;
        if (it + 1 < NIT) {
            const char* fs = sm + ((it + 1) & 3) * FPSTG;
            char* bs = sm + BFBASE + bfn * BFSTG;
            cvt_sts(fs + fpA, bs + AH_OFF + bfO, bs + AL_OFF + bfO);
            cvt_sts(fs + fpB, bs + BH_OFF + bfO, bs + BL_OFF + bfO);
            cvt_sts(fs + fpB + 4096, bs + BH_OFF + 3072 + bfO,
                    bs + BL_OFF + 3072 + bfO);
        }

        // 3) compute on bf stage it%3
        const uint32_t sb = sbase + BFBASE + bfc * BFSTG;
        uint32_t Ah0[4], Ah1[4], Al0[4], Al1[4];
        ldsm4(Ah0, sb + aOff);
        ldsm4(Ah1, sb + aOff + 16 * RSTRIDE);
        ldsm4(Al0, sb + aOff + (AL_OFF - AH_OFF));
        ldsm4(Al1, sb + aOff + (AL_OFF - AH_OFF) + 16 * RSTRIDE);
        uint32_t Bh0[4], Bh1[4], Bl0[4], Bl1[4];
        ldsm4(Bh0, sb + bOff);
        ldsm4(Bh1, sb + bOff + 16 * RSTRIDE);
        ldsm4(Bl0, sb + bOff + (BL_OFF - BH_OFF));
        ldsm4(Bl1, sb + bOff + (BL_OFF - BH_OFF) + 16 * RSTRIDE);

        const uint32_t* Bh[4] = { &Bh0[0], &Bh0[2], &Bh1[0], &Bh1[2] };
        const uint32_t* Bl[4] = { &Bl0[0], &Bl0[2], &Bl1[0], &Bl1[2] };
        const uint32_t* Ah[2] = { Ah0, Ah1 };
        const uint32_t* Al[2] = { Al0, Al1 };

        #pragma unroll
        for (int m = 0; m < 2; m++) {
            #pragma unroll
            for (int n = 0; n < 4; n++) {
                mma16816(acc[m][n], Ah[m], Bh[n][0], Bh[n][1]);   // hi*hi
                mma16816(acc[m][n], Ah[m], Bl[n][0], Bl[n][1]);   // hi*lo
                mma16816(acc[m][n], Al[m], Bh[n][0], Bh[n][1]);   // lo*hi
            }
        }
        bfc = bfn;
    }

    // Epilogue: c0,c1 -> row r0; c2,c3 -> row r0+8; cols 2q, 2q+1
    float* gp = g_partial[blockIdx.y];
    const int t0 = wm * 32;
    #pragma unroll
    for (int m = 0; m < 2; m++) {
        const int r0 = t0 + m * 16 + g;
        #pragma unroll
        for (int n = 0; n < 4; n++) {
            const int cb = nblk + wn * 32 + n * 8 + 2 * q;
            *(float2*)&gp[r0 * NCH + cb]       = make_float2(acc[m][n][0], acc[m][n][1]);
            *(float2*)&gp[(r0 + 8) * NCH + cb] = make_float2(acc[m][n][2], acc[m][n][3]);
        }
    }
}

// ---------------------------------------------------------------------------
// Kernel 2: reduce split-K partials -> g_pot
// ---------------------------------------------------------------------------
__global__ void reduce_kernel() {
    int i = blockIdx.x * blockDim.x + threadIdx.x;
    if (i < T_DIM * NCH) {
        float s = 0.0f;
        #pragma unroll
        for (int p = 0; p < SPLITK; p++) s += g_partial[p][i];
        g_pot[i] = s;
    }
}

// ---------------------------------------------------------------------------
// Kernel 3: winner selection (unchanged — proven exact)
// ---------------------------------------------------------------------------
__global__ void __launch_bounds__(1024)
winners_kernel() {
    __shared__ int   cnt_s[NCH];
    __shared__ float fpv_s[NCH];
    __shared__ float tot_s[NCH];
    __shared__ float rv[1024];
    __shared__ int   ri[1024];

    const int tid = threadIdx.x;

    for (int k = tid; k < NCH; k += 1024) {
        int cnt = 0;
        for (int t = 0; t < T_DIM; t++) {
            float o = g_pot[t * NCH + k];
            if (o > THRESHV) cnt++;
        }
        int fi = T_DIM - cnt;
        if (fi > T_DIM - 1) fi = T_DIM - 1;
        if (fi < 0) fi = 0;
        float o  = g_pot[fi * NCH + k];
        float fp = (o > THRESHV) ? o : 0.0f;
        cnt_s[k] = cnt;
        fpv_s[k] = fp;
    }
    __syncthreads();

    float m = 0.0f;
    for (int k = tid; k < NCH; k += 1024)
        m = fmaxf(m, (cnt_s[k] > 0) ? fpv_s[k] : 0.0f);
    rv[tid] = m;
    __syncthreads();
    for (int s = 512; s > 0; s >>= 1) {
        if (tid < s) rv[tid] = fmaxf(rv[tid], rv[tid + s]);
        __syncthreads();
    }
    float v = rv[0] * (float)T_DIM;
    __syncthreads();

    for (int k = tid; k < NCH; k += 1024) {
        float term = fpv_s[k] + v;
        float s = 0.0f;
        int c = cnt_s[k];
        for (int i = 0; i < c; i++) s += term;
        tot_s[k] = s;
        g_coef[k] = 0.0f;
    }
    __syncthreads();

    for (int it = 0; it < KWTA; it++) {
        float bv = -3.4e38f;
        int   bi = NCH;
        for (int k = tid; k < NCH; k += 1024) {
            float vv = tot_s[k];
            if (vv > bv || (vv == bv && k < bi)) { bv = vv; bi = k; }
        }
        rv[tid] = bv; ri[tid] = bi;
        __syncthreads();
        for (int s = 512; s > 0; s >>= 1) {
            if (tid < s) {
                if (rv[tid + s] > rv[tid] ||
                    (rv[tid + s] == rv[tid] && ri[tid + s] < ri[tid])) {
                    rv[tid] = rv[tid + s];
                    ri[tid] = ri[tid + s];
                }
            }
            __syncthreads();
        }
        if (tid == 0) {
            int wk = ri[0];
            if (rv[0] > 0.0f) g_coef[wk] = 1.0f;
            tot_s[wk] = -3.4e38f;
        }
        __syncthreads();
    }
}

// ---------------------------------------------------------------------------
// Kernel 4: final spikes
// ---------------------------------------------------------------------------
__global__ void output_kernel(float* __restrict__ out) {
    int i = blockIdx.x * blockDim.x + threadIdx.x;
    if (i < T_DIM * NCH) {
        float o = g_pot[i];
        out[i] = (o > THRESHV && g_coef[i & (NCH - 1)] > 0.0f) ? 1.0f : 0.0f;
    }
}

// ---------------------------------------------------------------------------
extern "C" void kernel_launch(void* const* d_in, const int* in_sizes, int n_in,
                              void* d_out, int out_size) {
    const float* rec = (const float*)d_in[0];   // (64, 1, 256, 256)
    const float* w   = (const float*)d_in[1];   // (2048, 1, 256, 256)
    float* out = (float*)d_out;                 // (64, 2048, 1, 1) float32

    cudaFuncSetAttribute(gemm_mma, cudaFuncAttributeMaxDynamicSharedMemorySize,
                         SMEM_TOTAL);
    dim3 grid(NCH / 128, SPLITK);               // (16, 16) = 256 CTAs
    gemm_mma<<<grid, 256, SMEM_TOTAL>>>(rec, w);
    reduce_kernel<<<(T_DIM * NCH + 255) / 256, 256>>>();
    winners_kernel<<<1, 1024>>>();
    output_kernel<<<(T_DIM * NCH + 255) / 256, 256>>>(out);
}